// round 15
// baseline (speedup 1.0000x reference)
#include <cuda_runtime.h>
#include <cuda_bf16.h>
#include <mma.h>
#include <cstdint>

using namespace nvcuda;

#define BB 32768
#define CC 1024
#define CH 256

typedef __nv_bfloat16 bf16;

// ---------------- device scratch (static, no allocation) ----------------
__device__ __align__(16) bf16  g_xn[(size_t)BB * CC];        // LN output, bf16
__device__ __align__(16) bf16  g_h1[(size_t)BB * CH];
__device__ __align__(16) bf16  g_t [(size_t)BB * CH];

__device__ __align__(16) bf16  g_Wdg[1024 * 512];            // [Wd | Wg] bf16
__device__ __align__(16) float g_bdg[512];
__device__ __align__(16) bf16  g_W1b[256 * 256];
__device__ __align__(16) float g_Wvof[256 * 256];            // fp32 Wv@Wo
__device__ __align__(16) float g_bvo[256];
__device__ __align__(16) float g_W23f[256 * 256];            // fp32 W2@(Wv@Wo)
__device__ __align__(16) float g_b23[256];
__device__ __align__(16) float g_Wu2f[256 * 1024];           // fp32 Wu + (Wu@Wld)@Wlu
__device__ __align__(16) float g_bu2[1024];
__device__ __align__(16) bf16  g_Wfin[256 * 1024];           // W23f @ Wu2f (bf16)
__device__ __align__(16) float g_bfin[1024];                 // b23 @ Wu2f + bu2
__device__ __align__(16) float g_T[256 * 16];

// ---------------- helpers ----------------
__device__ __forceinline__ float gelu_tanh(float x) {
    float x3 = x * x * x;
    return 0.5f * x * (1.0f + tanhf(0.7978845608028654f * (x + 0.044715f * x3)));
}

__device__ __forceinline__ void cp16(uint32_t d, const void* s) {
    asm volatile("cp.async.cg.shared.global [%0], [%1], 16;\n" :: "r"(d), "l"(s));
}

// ---------------- prep kernels ----------------
// Merged independent preps: Wdg pack (blocks 0..2047), W1 cvt (2048..2303), bdg (2304)
__global__ void prep_misc(const float* __restrict__ Wd, const float* __restrict__ Wg,
                          const float* __restrict__ bd, const float* __restrict__ bg,
                          const float* __restrict__ W1) {
    int b = blockIdx.x;
    if (b < 2048) {
        int idx = b * 256 + threadIdx.x;            // < 1024*512
        int k = idx >> 9, j = idx & 511;
        float v = (j < 256) ? Wd[k * 256 + j] : Wg[k * 256 + (j - 256)];
        g_Wdg[idx] = __float2bfloat16(v);
    } else if (b < 2304) {
        int i = (b - 2048) * 256 + threadIdx.x;     // < 256*256
        g_W1b[i] = __float2bfloat16(W1[i]);
    } else {
        int j = threadIdx.x;                        // 256 threads, 512 values
        g_bdg[j] = bd[j];
        g_bdg[256 + j] = bg[j];
    }
}

// Wvo = Wv @ Wo (fp32), 4 rows per CTA.
__global__ void prep_wvo(const float* __restrict__ Wv, const float* __restrict__ Wo,
                         const float* __restrict__ bv, const float* __restrict__ bo) {
    __shared__ float rows[4][256];
    int j = threadIdx.x;
    int i0 = blockIdx.x * 4;
    #pragma unroll
    for (int r = 0; r < 4; r++) rows[r][j] = Wv[(i0 + r) * 256 + j];
    __syncthreads();
    float acc[4] = {0.f, 0.f, 0.f, 0.f};
    #pragma unroll 4
    for (int k = 0; k < 256; k++) {
        float wo = Wo[k * 256 + j];
        acc[0] += rows[0][k] * wo;
        acc[1] += rows[1][k] * wo;
        acc[2] += rows[2][k] * wo;
        acc[3] += rows[3][k] * wo;
    }
    #pragma unroll
    for (int r = 0; r < 4; r++) g_Wvof[(i0 + r) * 256 + j] = acc[r];
    if (blockIdx.x == 0) {
        float b0 = 0.f, b1_ = 0.f;
        for (int k = 0; k < 256; k += 2) {
            b0  += bv[k] * Wo[k * 256 + j];
            b1_ += bv[k + 1] * Wo[(k + 1) * 256 + j];
        }
        g_bvo[j] = b0 + b1_ + bo[j];
    }
}

// W23f = W2 @ Wvo (fp32 out), 4 rows per CTA.
__global__ void prep_w2vo(const float* __restrict__ W2, const float* __restrict__ b2) {
    __shared__ float rows[4][256];
    int j = threadIdx.x;
    int i0 = blockIdx.x * 4;
    #pragma unroll
    for (int r = 0; r < 4; r++) rows[r][j] = W2[(i0 + r) * 256 + j];
    __syncthreads();
    float acc[4] = {0.f, 0.f, 0.f, 0.f};
    #pragma unroll 4
    for (int k = 0; k < 256; k++) {
        float wv = g_Wvof[k * 256 + j];
        acc[0] += rows[0][k] * wv;
        acc[1] += rows[1][k] * wv;
        acc[2] += rows[2][k] * wv;
        acc[3] += rows[3][k] * wv;
    }
    #pragma unroll
    for (int r = 0; r < 4; r++) g_W23f[(i0 + r) * 256 + j] = acc[r];
    if (blockIdx.x == 0) {
        float b0 = 0.f, b1_ = 0.f;
        for (int k = 0; k < 256; k += 2) {
            b0  += b2[k] * g_Wvof[k * 256 + j];
            b1_ += b2[k + 1] * g_Wvof[(k + 1) * 256 + j];
        }
        g_b23[j] = b0 + b1_ + g_bvo[j];
    }
}

__global__ void prep_T(const float* __restrict__ Wu, const float* __restrict__ Wld) {
    int i = blockIdx.x, t = threadIdx.x;
    int r = t & 15, seg = t >> 4;
    float acc = 0.f;
    int k0 = seg * 64;
    #pragma unroll 4
    for (int k = k0; k < k0 + 64; k++) acc += Wu[i * 1024 + k] * Wld[k * 16 + r];
    __shared__ float red[256];
    red[t] = acc;
    __syncthreads();
    if (seg == 0) {
        float s = 0.f;
        #pragma unroll
        for (int q = 0; q < 16; q++) s += red[q * 16 + r];
        g_T[i * 16 + r] = s;
    }
}

// Wu2f = Wu + (Wu@Wld)@Wlu  (fp32 out)
__global__ void prep_wu2f(const float* __restrict__ Wu, const float* __restrict__ Wlu) {
    int i = blockIdx.x;
    int j = blockIdx.y * 256 + threadIdx.x;
    __shared__ float Ti[16];
    if (threadIdx.x < 16) Ti[threadIdx.x] = g_T[i * 16 + threadIdx.x];
    __syncthreads();
    float acc = Wu[i * 1024 + j];
    #pragma unroll
    for (int r = 0; r < 16; r++) acc += Ti[r] * Wlu[r * 1024 + j];
    g_Wu2f[i * 1024 + j] = acc;
}

__global__ void prep_bu2(const float* __restrict__ bu, const float* __restrict__ Wld,
                         const float* __restrict__ Wlu) {
    __shared__ float s[16];
    int t = threadIdx.x;
    if (t < 16) {
        float a = 0.f;
        for (int k = 0; k < 1024; k++) a += bu[k] * Wld[k * 16 + t];
        s[t] = a;
    }
    __syncthreads();
    float acc = bu[t];
    #pragma unroll
    for (int r = 0; r < 16; r++) acc += s[r] * Wlu[r * 1024 + t];
    g_bu2[t] = acc;
}

// Wfin = W23f @ Wu2f (bf16 out); bfin = b23 @ Wu2f + bu2. 8 rows per CTA, grid (32,4).
__global__ void prep_wfinal() {
    __shared__ float rows[8][256];
    int j = blockIdx.y * 256 + threadIdx.x;
    int i0 = blockIdx.x * 8;
    #pragma unroll
    for (int r = 0; r < 8; r++) rows[r][threadIdx.x] = g_W23f[(i0 + r) * 256 + threadIdx.x];
    __syncthreads();
    float acc[8] = {0.f, 0.f, 0.f, 0.f, 0.f, 0.f, 0.f, 0.f};
    #pragma unroll 2
    for (int k = 0; k < 256; k++) {
        float w = g_Wu2f[k * 1024 + j];
        #pragma unroll
        for (int r = 0; r < 8; r++) acc[r] += rows[r][k] * w;
    }
    #pragma unroll
    for (int r = 0; r < 8; r++) g_Wfin[(i0 + r) * 1024 + j] = __float2bfloat16(acc[r]);
    if (blockIdx.x == 0) {
        float s = 0.f;
        for (int k = 0; k < 256; k++) s += g_b23[k] * g_Wu2f[k * 1024 + j];
        g_bfin[j] = s + g_bu2[j];
    }
}

// ---------------- LayerNorm: one warp per row ----------------
__global__ void ln_kernel(const float* __restrict__ x, const float* __restrict__ gw,
                          const float* __restrict__ bw) {
    int warp = threadIdx.x >> 5, lane = threadIdx.x & 31;
    int row = blockIdx.x * 8 + warp;
    const float4* xr = (const float4*)(x + (size_t)row * CC);
    float4 v[8];
    float s = 0.f, q = 0.f;
    #pragma unroll
    for (int i = 0; i < 8; i++) {
        v[i] = xr[lane + 32 * i];
        s += v[i].x + v[i].y + v[i].z + v[i].w;
        q += v[i].x * v[i].x + v[i].y * v[i].y + v[i].z * v[i].z + v[i].w * v[i].w;
    }
    #pragma unroll
    for (int o = 16; o; o >>= 1) {
        s += __shfl_xor_sync(0xffffffffu, s, o);
        q += __shfl_xor_sync(0xffffffffu, q, o);
    }
    float mu = s * (1.0f / 1024.0f);
    float var = q * (1.0f / 1024.0f) - mu * mu;
    float rs = rsqrtf(var + 1e-5f);
    uint2* dst = (uint2*)(g_xn + (size_t)row * CC);
    const float4* g4 = (const float4*)gw;
    const float4* b4 = (const float4*)bw;
    #pragma unroll
    for (int i = 0; i < 8; i++) {
        int idx = lane + 32 * i;
        float4 gg = g4[idx], bb = b4[idx];
        float y0 = (v[i].x - mu) * rs * gg.x + bb.x;
        float y1 = (v[i].y - mu) * rs * gg.y + bb.y;
        float y2 = (v[i].z - mu) * rs * gg.z + bb.z;
        float y3 = (v[i].w - mu) * rs * gg.w + bb.w;
        __nv_bfloat162 lo = __floats2bfloat162_rn(y0, y1);
        __nv_bfloat162 hi = __floats2bfloat162_rn(y2, y3);
        uint2 u;
        u.x = *reinterpret_cast<unsigned*>(&lo);
        u.y = *reinterpret_cast<unsigned*>(&hi);
        dst[idx] = u;
    }
}

// ================= pipelined smem GEMM machinery (measured-fast clones only) ====
#define AS2 5120    // 128 * 40 bf16 per A stage
#define BS2 4352    // 32 * 136 bf16 per B stage
#define SMEM_BYTES 37888

// ---------------- gemm1 fused with GLU + depthwise affine (frozen, 196us) ------
__global__ void __launch_bounds__(512, 2)
gemm1s_glu_kernel(const float* __restrict__ dw_w, const float* __restrict__ dw_b) {
    __shared__ __align__(16) char sm[SMEM_BYTES];
    bf16* sA = reinterpret_cast<bf16*>(sm);
    bf16* sB = reinterpret_cast<bf16*>(sm + 2 * AS2 * 2);
    uint32_t sA_u = (uint32_t)__cvta_generic_to_shared(sA);
    uint32_t sB_u = (uint32_t)__cvta_generic_to_shared(sB);

    int tid = threadIdx.x;
    int warp = tid >> 5;
    int mw = warp >> 2, nw = warp & 3;
    int row0 = blockIdx.y * 128;
    int base = blockIdx.x * 64;                 // d-col base (g at 256+base)

    wmma::fragment<wmma::accumulator, 16, 16, 16, float> cd[2], cg[2];
    #pragma unroll
    for (int i = 0; i < 2; i++) { wmma::fill_fragment(cd[i], 0.0f); wmma::fill_fragment(cg[i], 0.0f); }

    int ar = tid >> 2, ac = (tid & 3) << 3;     // A: 128 x 32
    int br = tid >> 4, bc = (tid & 15) << 3;    // B: 32 x 128 virtual (d | g)
    int bcol = (bc < 64) ? (base + bc) : (256 + base + (bc - 64));

    auto load_tile = [&](int stage, int k0) {
        cp16(sA_u + (stage * AS2 + ar * 40 + ac) * 2,
             g_xn + (size_t)(row0 + ar) * 1024 + k0 + ac);
        cp16(sB_u + (stage * BS2 + br * 136 + bc) * 2,
             g_Wdg + (size_t)(k0 + br) * 512 + bcol);
        asm volatile("cp.async.commit_group;\n");
    };

    load_tile(0, 0);
    const int KT = 32;                          // K = 1024 / 32
    for (int kt = 0; kt < KT; kt++) {
        int cur = kt & 1;
        if (kt + 1 < KT) {
            load_tile(cur ^ 1, (kt + 1) * 32);
            asm volatile("cp.async.wait_group 1;\n");
        } else {
            asm volatile("cp.async.wait_group 0;\n");
        }
        __syncthreads();
        #pragma unroll
        for (int ks = 0; ks < 2; ks++) {
            wmma::fragment<wmma::matrix_a, 16, 16, 16, bf16, wmma::row_major> a0, a1;
            wmma::fragment<wmma::matrix_b, 16, 16, 16, bf16, wmma::row_major> bd_, bg_;
            const bf16* pa = sA + cur * AS2 + (mw * 32) * 40 + ks * 16;
            wmma::load_matrix_sync(a0, pa, 40);
            wmma::load_matrix_sync(a1, pa + 16 * 40, 40);
            const bf16* pb = sB + cur * BS2 + (ks * 16) * 136;
            wmma::load_matrix_sync(bd_, pb + nw * 16, 136);
            wmma::load_matrix_sync(bg_, pb + 64 + nw * 16, 136);
            wmma::mma_sync(cd[0], a0, bd_, cd[0]);
            wmma::mma_sync(cd[1], a1, bd_, cd[1]);
            wmma::mma_sync(cg[0], a0, bg_, cg[0]);
            wmma::mma_sync(cg[1], a1, bg_, cg[1]);
        }
        __syncthreads();
    }

    // CTA-wide coalesced epilogue: two row-strip passes
    float* sC = reinterpret_cast<float*>(sm);
    #pragma unroll
    for (int i = 0; i < 2; i++) {
        __syncthreads();
        wmma::store_matrix_sync(sC + (mw * 16) * 136 + nw * 16,      cd[i], 136, wmma::mem_row_major);
        wmma::store_matrix_sync(sC + (mw * 16) * 136 + 68 + nw * 16, cg[i], 136, wmma::mem_row_major);
        __syncthreads();
        #pragma unroll
        for (int e = tid; e < 64 * 16; e += 512) {
            int r = e >> 4;
            int c4 = (e & 15) << 2;
            int grow = row0 + (r >> 4) * 32 + i * 16 + (r & 15);
            int gcol = base + c4;
            float4 bd4 = *(const float4*)(g_bdg + gcol);
            float4 bg4 = *(const float4*)(g_bdg + 256 + gcol);
            float4 w4  = *(const float4*)(dw_w + gcol);
            float4 db4 = *(const float4*)(dw_b + gcol);
            float d0 = sC[r * 136 + c4 + 0] + bd4.x;
            float d1 = sC[r * 136 + c4 + 1] + bd4.y;
            float d2 = sC[r * 136 + c4 + 2] + bd4.z;
            float d3 = sC[r * 136 + c4 + 3] + bd4.w;
            float q0 = sC[r * 136 + 68 + c4 + 0] + bg4.x;
            float q1 = sC[r * 136 + 68 + c4 + 1] + bg4.y;
            float q2 = sC[r * 136 + 68 + c4 + 2] + bg4.z;
            float q3 = sC[r * 136 + 68 + c4 + 3] + bg4.w;
            float h0 = d0 * (1.0f / (1.0f + __expf(-q0))) * w4.x + db4.x;
            float h1 = d1 * (1.0f / (1.0f + __expf(-q1))) * w4.y + db4.y;
            float h2 = d2 * (1.0f / (1.0f + __expf(-q2))) * w4.z + db4.z;
            float h3 = d3 * (1.0f / (1.0f + __expf(-q3))) * w4.w + db4.w;
            __nv_bfloat162 lo = __floats2bfloat162_rn(h0, h1);
            __nv_bfloat162 hi = __floats2bfloat162_rn(h2, h3);
            uint2 u;
            u.x = *reinterpret_cast<unsigned*>(&lo);
            u.y = *reinterpret_cast<unsigned*>(&hi);
            *(uint2*)(g_h1 + (size_t)(grow) * 256 + gcol) = u;
        }
    }
}

// ---------------- pipelined gemm2 (proven clone) -------------------------------
__global__ void __launch_bounds__(512, 2)
gemm2s_kernel(const float* __restrict__ b1) {
    __shared__ __align__(16) char sm[SMEM_BYTES];
    bf16* sA = reinterpret_cast<bf16*>(sm);
    bf16* sB = reinterpret_cast<bf16*>(sm + 2 * AS2 * 2);
    uint32_t sA_u = (uint32_t)__cvta_generic_to_shared(sA);
    uint32_t sB_u = (uint32_t)__cvta_generic_to_shared(sB);

    int tid = threadIdx.x;
    int warp = tid >> 5;
    int mw = warp >> 2, nw = warp & 3;
    int row0 = blockIdx.y * 128;
    int col0 = blockIdx.x * 128;

    wmma::fragment<wmma::accumulator, 16, 16, 16, float> c[2][2];
    #pragma unroll
    for (int i = 0; i < 2; i++)
        #pragma unroll
        for (int j = 0; j < 2; j++) wmma::fill_fragment(c[i][j], 0.0f);

    int ar = tid >> 2, ac = (tid & 3) << 3;
    int br = tid >> 4, bc = (tid & 15) << 3;

    auto load_tile = [&](int stage, int k0) {
        cp16(sA_u + (stage * AS2 + ar * 40 + ac) * 2,
             g_h1 + (size_t)(row0 + ar) * 256 + k0 + ac);
        cp16(sB_u + (stage * BS2 + br * 136 + bc) * 2,
             g_W1b + (size_t)(k0 + br) * 256 + col0 + bc);
        asm volatile("cp.async.commit_group;\n");
    };

    load_tile(0, 0);
    const int KT = 8;
    for (int kt = 0; kt < KT; kt++) {
        int cur = kt & 1;
        if (kt + 1 < KT) {
            load_tile(cur ^ 1, (kt + 1) * 32);
            asm volatile("cp.async.wait_group 1;\n");
        } else {
            asm volatile("cp.async.wait_group 0;\n");
        }
        __syncthreads();
        #pragma unroll
        for (int ks = 0; ks < 2; ks++) {
            wmma::fragment<wmma::matrix_a, 16, 16, 16, bf16, wmma::row_major> a0, a1;
            wmma::fragment<wmma::matrix_b, 16, 16, 16, bf16, wmma::row_major> b0, b1f;
            const bf16* pa = sA + cur * AS2 + (mw * 32) * 40 + ks * 16;
            wmma::load_matrix_sync(a0, pa, 40);
            wmma::load_matrix_sync(a1, pa + 16 * 40, 40);
            const bf16* pb = sB + cur * BS2 + (ks * 16) * 136 + nw * 32;
            wmma::load_matrix_sync(b0, pb, 136);
            wmma::load_matrix_sync(b1f, pb + 16, 136);
            wmma::mma_sync(c[0][0], a0, b0, c[0][0]);
            wmma::mma_sync(c[0][1], a0, b1f, c[0][1]);
            wmma::mma_sync(c[1][0], a1, b0, c[1][0]);
            wmma::mma_sync(c[1][1], a1, b1f, c[1][1]);
        }
        __syncthreads();
    }

    float* sC = reinterpret_cast<float*>(sm);
    #pragma unroll
    for (int i = 0; i < 2; i++) {
        __syncthreads();
        wmma::store_matrix_sync(sC + (mw * 16) * 132 + nw * 32,      c[i][0], 132, wmma::mem_row_major);
        wmma::store_matrix_sync(sC + (mw * 16) * 132 + nw * 32 + 16, c[i][1], 132, wmma::mem_row_major);
        __syncthreads();
        #pragma unroll
        for (int e = tid; e < 64 * 32; e += 512) {
            int r = e >> 5;
            int c4 = (e & 31) << 2;
            int grow = row0 + (r >> 4) * 32 + i * 16 + (r & 15);
            int gcol = col0 + c4;
            float4 bv = *(const float4*)(b1 + gcol);
            float v0 = gelu_tanh(sC[r * 132 + c4 + 0] + bv.x);
            float v1 = gelu_tanh(sC[r * 132 + c4 + 1] + bv.y);
            float v2 = gelu_tanh(sC[r * 132 + c4 + 2] + bv.z);
            float v3 = gelu_tanh(sC[r * 132 + c4 + 3] + bv.w);
            __nv_bfloat162 lo = __floats2bfloat162_rn(v0, v1);
            __nv_bfloat162 hi = __floats2bfloat162_rn(v2, v3);
            uint2 u;
            u.x = *reinterpret_cast<unsigned*>(&lo);
            u.y = *reinterpret_cast<unsigned*>(&hi);
            *(uint2*)(g_t + (size_t)grow * 256 + gcol) = u;
        }
    }
}

// ---------------- pipelined gemmF (clone of proven gemm5p; A=g_t, B=g_Wfin) ----
__global__ void __launch_bounds__(512, 2)
gemmF_kernel(float* __restrict__ out, const float* __restrict__ x) {
    __shared__ __align__(16) char sm[SMEM_BYTES];
    bf16* sA = reinterpret_cast<bf16*>(sm);
    bf16* sB = reinterpret_cast<bf16*>(sm + 2 * AS2 * 2);
    uint32_t sA_u = (uint32_t)__cvta_generic_to_shared(sA);
    uint32_t sB_u = (uint32_t)__cvta_generic_to_shared(sB);

    int tid = threadIdx.x;
    int warp = tid >> 5;
    int mw = warp >> 2, nw = warp & 3;
    int row0 = blockIdx.y * 128;
    int col0 = blockIdx.x * 128;

    wmma::fragment<wmma::accumulator, 16, 16, 16, float> c[2][2];
    #pragma unroll
    for (int i = 0; i < 2; i++)
        #pragma unroll
        for (int j = 0; j < 2; j++) wmma::fill_fragment(c[i][j], 0.0f);

    int ar = tid >> 2, ac = (tid & 3) << 3;
    int br = tid >> 4, bc = (tid & 15) << 3;

    auto load_tile = [&](int stage, int k0) {
        cp16(sA_u + (stage * AS2 + ar * 40 + ac) * 2,
             g_t + (size_t)(row0 + ar) * 256 + k0 + ac);
        cp16(sB_u + (stage * BS2 + br * 136 + bc) * 2,
             g_Wfin + (size_t)(k0 + br) * 1024 + col0 + bc);
        asm volatile("cp.async.commit_group;\n");
    };

    load_tile(0, 0);
    const int KT = 8;
    for (int kt = 0; kt < KT; kt++) {
        int cur = kt & 1;
        if (kt + 1 < KT) {
            load_tile(cur ^ 1, (kt + 1) * 32);
            asm volatile("cp.async.wait_group 1;\n");
        } else {
            asm volatile("cp.async.wait_group 0;\n");
        }
        __syncthreads();
        #pragma unroll
        for (int ks = 0; ks < 2; ks++) {
            wmma::fragment<wmma::matrix_a, 16, 16, 16, bf16, wmma::row_major> a0, a1;
            wmma::fragment<wmma::matrix_b, 16, 16, 16, bf16, wmma::row_major> b0, b1f;
            const bf16* pa = sA + cur * AS2 + (mw * 32) * 40 + ks * 16;
            wmma::load_matrix_sync(a0, pa, 40);
            wmma::load_matrix_sync(a1, pa + 16 * 40, 40);
            const bf16* pb = sB + cur * BS2 + (ks * 16) * 136 + nw * 32;
            wmma::load_matrix_sync(b0, pb, 136);
            wmma::load_matrix_sync(b1f, pb + 16, 136);
            wmma::mma_sync(c[0][0], a0, b0, c[0][0]);
            wmma::mma_sync(c[0][1], a0, b1f, c[0][1]);
            wmma::mma_sync(c[1][0], a1, b0, c[1][0]);
            wmma::mma_sync(c[1][1], a1, b1f, c[1][1]);
        }
        __syncthreads();
    }

    float* sC = reinterpret_cast<float*>(sm);
    #pragma unroll
    for (int i = 0; i < 2; i++) {
        __syncthreads();
        wmma::store_matrix_sync(sC + (mw * 16) * 132 + nw * 32,      c[i][0], 132, wmma::mem_row_major);
        wmma::store_matrix_sync(sC + (mw * 16) * 132 + nw * 32 + 16, c[i][1], 132, wmma::mem_row_major);
        __syncthreads();
        #pragma unroll
        for (int e = tid; e < 64 * 32; e += 512) {
            int r = e >> 5;
            int c4 = (e & 31) << 2;
            int grow = row0 + (r >> 4) * 32 + i * 16 + (r & 15);
            int gcol = col0 + c4;
            float4 bv = *(const float4*)(g_bfin + gcol);
            float v0 = sC[r * 132 + c4 + 0] + bv.x;
            float v1 = sC[r * 132 + c4 + 1] + bv.y;
            float v2 = sC[r * 132 + c4 + 2] + bv.z;
            float v3 = sC[r * 132 + c4 + 3] + bv.w;
            float4 xv = *(const float4*)(x + (size_t)grow * 1024 + gcol);
            float4 o;
            o.x = 0.5f * v0 + 0.5f * xv.x;
            o.y = 0.5f * v1 + 0.5f * xv.y;
            o.z = 0.5f * v2 + 0.5f * xv.z;
            o.w = 0.5f * v3 + 0.5f * xv.w;
            *(float4*)(out + (size_t)grow * 1024 + gcol) = o;
        }
    }
}

// ---------------- launcher ----------------
extern "C" void kernel_launch(void* const* d_in, const int* in_sizes, int n_in,
                              void* d_out, int out_size) {
    const float* x    = (const float*)d_in[0];
    const float* ln_g = (const float*)d_in[1];
    const float* ln_b = (const float*)d_in[2];
    const float* Wd   = (const float*)d_in[3];
    const float* bd   = (const float*)d_in[4];
    const float* Wg   = (const float*)d_in[5];
    const float* bg   = (const float*)d_in[6];
    const float* dw_w = (const float*)d_in[7];
    const float* dw_b = (const float*)d_in[8];
    const float* W1   = (const float*)d_in[9];
    const float* b1   = (const float*)d_in[10];
    const float* W2   = (const float*)d_in[11];
    const float* b2   = (const float*)d_in[12];
    // d_in[13..16] = Wq,bq,Wk,bk : dead (softmax over a single key == 1)
    const float* Wv   = (const float*)d_in[17];
    const float* bv   = (const float*)d_in[18];
    const float* Wo   = (const float*)d_in[19];
    const float* bo   = (const float*)d_in[20];
    const float* Wu   = (const float*)d_in[21];
    const float* bu   = (const float*)d_in[22];
    const float* Wld  = (const float*)d_in[23];
    const float* Wlu  = (const float*)d_in[24];
    float* out = (float*)d_out;

    prep_misc<<<2305, 256>>>(Wd, Wg, bd, bg, W1);                     // 1
    prep_wvo<<<64, 256>>>(Wv, Wo, bv, bo);                            // 2
    ln_kernel<<<BB / 8, 256>>>(x, ln_g, ln_b);                        // 3
    gemm1s_glu_kernel<<<dim3(4, BB / 128), 512>>>(dw_w, dw_b);        // 4 (ncu slot)
    gemm2s_kernel<<<dim3(2, BB / 128), 512>>>(b1);                    // 5
    prep_w2vo<<<64, 256>>>(W2, b2);                                   // 6
    prep_T<<<256, 256>>>(Wu, Wld);                                    // 7
    prep_wu2f<<<dim3(256, 4), 256>>>(Wu, Wlu);                        // 8
    prep_bu2<<<1, 1024>>>(bu, Wld, Wlu);                              // 9
    prep_wfinal<<<dim3(32, 4), 256>>>();                              // 10
    gemmF_kernel<<<dim3(8, BB / 128), 512>>>(out, x);                 // 11
}